// round 16
// baseline (speedup 1.0000x reference)
#include <cuda_runtime.h>
#include <math.h>
#include <stdint.h>

#define L_SEQ 32768
#define H_DIM 512
#define P_DIM 256
#define VPT 8
#define SCAN_T 256
#define CHUNK (SCAN_T * VPT)        // 2048
#define NCHUNK (L_SEQ / CHUNK)      // 16

// fp32 scratch planes [P][L]: Bu written by gemm1, read by scan.
__device__ float g_x_re[(size_t)P_DIM * L_SEQ];
__device__ float g_x_im[(size_t)P_DIM * L_SEQ];

// decoupled-lookback state
__device__ float g_lbA[P_DIM * NCHUNK * 4];   // chunk aggregate (Ar,Ai,br,bi)
__device__ float g_lbP[P_DIM * NCHUNK * 4];   // chunk inclusive prefix
__device__ int   g_lbF[P_DIM * NCHUNK];       // 0 none, 1 agg ready, 2 prefix ready

// pre-converted bf16 operand images, NATURAL word order: [k16-group][row][8 words]
__device__ uint32_t g_up[(size_t)32 * L_SEQ * 8];        // u:  kg 0..31 (h), row l
__device__ uint32_t g_Bp[2 * 32 * 256 * 8];              // B:  plane, kg (h), row p
__device__ uint32_t g_Cp[2 * 16 * 512 * 8];              // C:  plane, kg (p), row h
// bf16 scanned state planes [P][L] (scan -> pack_x)
__device__ uint16_t g_xrbf[(size_t)P_DIM * L_SEQ];
__device__ uint16_t g_xibf[(size_t)P_DIM * L_SEQ];
// packed gemm2 A image: [plane][kg 0..15][l][8 words], im plane pre-negated
__device__ uint32_t g_xp[(size_t)2 * 16 * L_SEQ * 8];

// ---------------- common helpers ----------------

__device__ __forceinline__ void combine_right(float& Ar, float& Ai, float& br, float& bi,
                                              float pAr, float pAi, float pbr, float pbi)
{
    float nAr = Ar*pAr - Ai*pAi;
    float nAi = Ar*pAi + Ai*pAr;
    float nbr = Ar*pbr - Ai*pbi + br;
    float nbi = Ar*pbi + Ai*pbr + bi;
    Ar = nAr; Ai = nAi; br = nbr; bi = nbi;
}

__device__ __forceinline__ void lambda_bar(float lre, float lim, float Dl, float& Ar, float& Ai)
{
    float e = expf(lre * Dl);
    float s, c;
    sincosf(lim * Dl, &s, &c);
    Ar = e * c;
    Ai = e * s;
}

__device__ __forceinline__ uint32_t packbf(float lo, float hi)
{
    uint32_t r;
    asm("cvt.rn.bf16x2.f32 %0, %1, %2;" : "=r"(r) : "f"(hi), "f"(lo));
    return r;
}

__device__ __forceinline__ void mma_bf16(float* d, const uint32_t* a, uint32_t b0, uint32_t b1)
{
    asm volatile(
        "mma.sync.aligned.m16n8k16.row.col.f32.bf16.bf16.f32 "
        "{%0,%1,%2,%3}, {%4,%5,%6,%7}, {%8,%9}, {%0,%1,%2,%3};"
        : "+f"(d[0]), "+f"(d[1]), "+f"(d[2]), "+f"(d[3])
        : "r"(a[0]), "r"(a[1]), "r"(a[2]), "r"(a[3]), "r"(b0), "r"(b1));
}

#define LDSM_X4(r0, r1, r2, r3, addr) \
    asm volatile("ldmatrix.sync.aligned.m8n8.x4.shared.b16 {%0,%1,%2,%3}, [%4];" \
                 : "=r"(r0), "=r"(r1), "=r"(r2), "=r"(r3) : "r"(addr))

__device__ __forceinline__ uint32_t smem_u32(const void* p) {
    uint32_t a;
    asm("{ .reg .u64 t; cvta.to.shared.u64 t, %1; cvt.u32.u64 %0, t; }" : "=r"(a) : "l"(p));
    return a;
}

// byte offset of (row, k-half) within a kg region; 16B-granule XOR swizzle
__device__ __forceinline__ uint32_t swz(int row, int half)
{
    return (uint32_t)(row * 32 + ((half ^ ((row >> 2) & 1)) << 4));
}

#define CP_ASYNC16(dst, src) \
    asm volatile("cp.async.cg.shared.global [%0], [%1], 16;" :: "r"(dst), "l"(src) : "memory")
#define CP_COMMIT() asm volatile("cp.async.commit_group;" ::: "memory")
#define CP_WAIT1()  asm volatile("cp.async.wait_group 1;" ::: "memory")
#define CP_WAIT0()  asm volatile("cp.async.wait_group 0;" ::: "memory")

// chunk-index swizzle (chunk = row*2 + half)
__device__ __forceinline__ int cswz(int c) { return c ^ ((c >> 3) & 1); }

// ======================== converters (natural word order) ========================
__global__ __launch_bounds__(256) void convert_u_p(const float* __restrict__ u)
{
    int id = blockIdx.x * 256 + threadIdx.x;   // 32 kg x 32768 l
    int kg = id >> 15;
    int l  = id & 32767;
    const float* src = u + (size_t)l * H_DIM + kg * 16;
    float4 v0 = *(const float4*)(src + 0);
    float4 v1 = *(const float4*)(src + 4);
    float4 v2 = *(const float4*)(src + 8);
    float4 v3 = *(const float4*)(src + 12);
    uint32_t* dst = g_up + ((size_t)kg * L_SEQ + l) * 8;
    *(uint4*)(dst)     = make_uint4(packbf(v0.x, v0.y), packbf(v0.z, v0.w),
                                    packbf(v1.x, v1.y), packbf(v1.z, v1.w));
    *(uint4*)(dst + 4) = make_uint4(packbf(v2.x, v2.y), packbf(v2.z, v2.w),
                                    packbf(v3.x, v3.y), packbf(v3.z, v3.w));
}

__global__ __launch_bounds__(256) void convert_B_p(
    const float* __restrict__ Bre, const float* __restrict__ Bim)
{
    int kg = blockIdx.x;
    int pl = blockIdx.y;
    int p  = threadIdx.x;
    const float* src = (pl ? Bim : Bre) + (size_t)p * H_DIM + kg * 16;
    float4 v0 = *(const float4*)(src + 0);
    float4 v1 = *(const float4*)(src + 4);
    float4 v2 = *(const float4*)(src + 8);
    float4 v3 = *(const float4*)(src + 12);
    uint32_t* dst = g_Bp + ((size_t)(pl * 32 + kg) * 256 + p) * 8;
    *(uint4*)(dst)     = make_uint4(packbf(v0.x, v0.y), packbf(v0.z, v0.w),
                                    packbf(v1.x, v1.y), packbf(v1.z, v1.w));
    *(uint4*)(dst + 4) = make_uint4(packbf(v2.x, v2.y), packbf(v2.z, v2.w),
                                    packbf(v3.x, v3.y), packbf(v3.z, v3.w));
}

__global__ __launch_bounds__(512) void convert_C_p(
    const float* __restrict__ Cre, const float* __restrict__ Cim)
{
    int kg = blockIdx.x;
    int pl = blockIdx.y;
    int h  = threadIdx.x;
    const float* src = (pl ? Cim : Cre) + (size_t)h * P_DIM + kg * 16;
    float4 v0 = *(const float4*)(src + 0);
    float4 v1 = *(const float4*)(src + 4);
    float4 v2 = *(const float4*)(src + 8);
    float4 v3 = *(const float4*)(src + 12);
    uint32_t* dst = g_Cp + ((size_t)(pl * 16 + kg) * 512 + h) * 8;
    *(uint4*)(dst)     = make_uint4(packbf(v0.x, v0.y), packbf(v0.z, v0.w),
                                    packbf(v1.x, v1.y), packbf(v1.z, v1.w));
    *(uint4*)(dst + 4) = make_uint4(packbf(v2.x, v2.y), packbf(v2.z, v2.w),
                                    packbf(v3.x, v3.y), packbf(v3.z, v3.w));
}

// ======================== GEMM1 (unchanged from R15) ========================
#define G1_BUFB 12288
#define G1_SMEM_BYTES (3 * G1_BUFB)

__global__ __launch_bounds__(256, 3) void gemm1(
    const float* __restrict__ dtv, const float* __restrict__ Lre_g, const float* __restrict__ Lim_g,
    const float* __restrict__ logstep)
{
    extern __shared__ uint32_t sm1[];
    const uint32_t smb = smem_u32(sm1);
    const int tid = threadIdx.x;
    const int wid = tid >> 5, lane = tid & 31;
    const int g = lane >> 2, t = lane & 3;
    const int wm = wid >> 1, wn = wid & 1;
    const int bm = blockIdx.y * 128;
    const int bn = blockIdx.x * 32;

    const int qr = lane & 7, sel = lane >> 3;
    const uint32_t aoff0 = swz(wm * 32 + 0 * 16 + (sel & 1) * 8 + qr, sel >> 1);
    const uint32_t aoff1 = swz(wm * 32 + 1 * 16 + (sel & 1) * 8 + qr, sel >> 1);
    const uint32_t boff  = swz(wn * 16 + (sel >> 1) * 8 + qr, sel & 1);

    float accr[2][2][4];
    float acci[2][2][4];
#pragma unroll
    for (int i = 0; i < 2; i++)
#pragma unroll
        for (int j = 0; j < 2; j++)
#pragma unroll
            for (int r = 0; r < 4; r++) { accr[i][j][r] = 0.0f; acci[i][j][r] = 0.0f; }

    auto copy_step = [&](int s, int buf) {
        uint32_t sb = smb + buf * G1_BUFB;
        int kg = 2 * s;
#pragma unroll
        for (int j = 0; j < 2; j++) {
            int c = tid + j * 256;
            int grp = c >> 8, off = c & 255;
            CP_ASYNC16(sb + grp * 4096 + cswz(off) * 16,
                       (const char*)(g_up + ((size_t)(kg + grp) * L_SEQ + bm) * 8) + off * 16);
        }
        {
            int bsel = tid >> 7, boff2 = tid & 127;
            int grp = boff2 >> 6, off = boff2 & 63;
            CP_ASYNC16(sb + 8192 + bsel * 2048 + grp * 1024 + cswz(off) * 16,
                       (const char*)(g_Bp + ((size_t)(bsel * 32 + kg + grp) * 256 + bn) * 8) + off * 16);
        }
    };

    copy_step(0, 0); CP_COMMIT();
    copy_step(1, 1); CP_COMMIT();

    for (int s = 0; s < 16; s++) {
        if (s < 15) CP_WAIT1(); else CP_WAIT0();
        __syncthreads();
        if (s + 2 < 16) { copy_step(s + 2, (s + 2) % 3); CP_COMMIT(); }

        const uint32_t curb = smb + (s % 3) * G1_BUFB;
#pragma unroll
        for (int k16 = 0; k16 < 2; k16++) {
            uint32_t a[2][4];
            LDSM_X4(a[0][0], a[0][1], a[0][2], a[0][3], curb + k16 * 4096 + aoff0);
            LDSM_X4(a[1][0], a[1][1], a[1][2], a[1][3], curb + k16 * 4096 + aoff1);
            uint32_t brg[4], big[4];
            uint32_t bb = curb + 8192 + k16 * 1024 + boff;
            LDSM_X4(brg[0], brg[1], brg[2], brg[3], bb);
            LDSM_X4(big[0], big[1], big[2], big[3], bb + 2048);
#pragma unroll
            for (int nt = 0; nt < 2; nt++) {
#pragma unroll
                for (int mt = 0; mt < 2; mt++) {
                    mma_bf16(accr[mt][nt], a[mt], brg[nt * 2], brg[nt * 2 + 1]);
                    mma_bf16(acci[mt][nt], a[mt], big[nt * 2], big[nt * 2 + 1]);
                }
            }
        }
    }

    float dts[2][2];
#pragma unroll
    for (int mt = 0; mt < 2; mt++)
#pragma unroll
        for (int rh = 0; rh < 2; rh++)
            dts[mt][rh] = dtv[bm + wm * 32 + mt * 16 + g + rh * 8];

#pragma unroll
    for (int nt = 0; nt < 2; nt++) {
#pragma unroll
        for (int c = 0; c < 2; c++) {
            int p = bn + wn * 16 + nt * 8 + 2 * t + c;
            float lre = Lre_g[p], lim = Lim_g[p];
            float stp = expf(logstep[p]);
            float inv = 1.0f / (lre * lre + lim * lim);
#pragma unroll
            for (int mt = 0; mt < 2; mt++) {
#pragma unroll
                for (int rh = 0; rh < 2; rh++) {
                    int l = bm + wm * 32 + mt * 16 + g + rh * 8;
                    float Dl = dts[mt][rh] * stp;
                    float Ar, Ai;
                    lambda_bar(lre, lim, Dl, Ar, Ai);
                    float gr = ((Ar - 1.0f) * lre + Ai * lim) * inv;
                    float gi = (Ai * lre - (Ar - 1.0f) * lim) * inv;
                    int reg = rh * 2 + c;
                    float ar = accr[mt][nt][reg], ai = acci[mt][nt][reg];
                    size_t o = (size_t)p * L_SEQ + l;
                    g_x_re[o] = gr * ar - gi * ai;
                    g_x_im[o] = gr * ai + gi * ar;
                }
            }
        }
    }
}

// ======================== flag init (runs every launch / graph replay) ========================
__global__ __launch_bounds__(256) void init_flags()
{
    g_lbF[blockIdx.x * 256 + threadIdx.x] = 0;
}

// ======================== Fused single-pass scan (decoupled lookback) ========================
__global__ __launch_bounds__(SCAN_T) void scan_fused(
    const float* __restrict__ dtv, const float* __restrict__ Lre_g,
    const float* __restrict__ Lim_g, const float* __restrict__ logstep)
{
    const int p = blockIdx.y;
    const int chunk = blockIdx.x;
    const int tid = threadIdx.x;
    const int l0 = chunk * CHUNK + tid * VPT;
    const int lane = tid & 31, wid = tid >> 5;

    const float lre = Lre_g[p], lim = Lim_g[p];
    const float stp = expf(logstep[p]);
    const float* xr = g_x_re + (size_t)p * L_SEQ + l0;
    const float* xi = g_x_im + (size_t)p * L_SEQ + l0;

    float dt[VPT], bvr[VPT], bvi[VPT];
    {
        float4 d0 = *(const float4*)(dtv + l0);
        float4 d1 = *(const float4*)(dtv + l0 + 4);
        dt[0]=d0.x; dt[1]=d0.y; dt[2]=d0.z; dt[3]=d0.w;
        dt[4]=d1.x; dt[5]=d1.y; dt[6]=d1.z; dt[7]=d1.w;
        float4 r0 = *(const float4*)(xr), r1 = *(const float4*)(xr + 4);
        bvr[0]=r0.x; bvr[1]=r0.y; bvr[2]=r0.z; bvr[3]=r0.w;
        bvr[4]=r1.x; bvr[5]=r1.y; bvr[6]=r1.z; bvr[7]=r1.w;
        float4 i0 = *(const float4*)(xi), i1 = *(const float4*)(xi + 4);
        bvi[0]=i0.x; bvi[1]=i0.y; bvi[2]=i0.z; bvi[3]=i0.w;
        bvi[4]=i1.x; bvi[5]=i1.y; bvi[6]=i1.z; bvi[7]=i1.w;
    }

    // serial inclusive within thread
    float IAr[VPT], IAi[VPT], Ibr[VPT], Ibi[VPT];
    {
        float Aer, Aei;
        lambda_bar(lre, lim, dt[0] * stp, Aer, Aei);
        IAr[0] = Aer; IAi[0] = Aei; Ibr[0] = bvr[0]; Ibi[0] = bvi[0];
#pragma unroll
        for (int e = 1; e < VPT; e++) {
            lambda_bar(lre, lim, dt[e] * stp, Aer, Aei);
            IAr[e] = Aer*IAr[e-1] - Aei*IAi[e-1];
            IAi[e] = Aer*IAi[e-1] + Aei*IAr[e-1];
            Ibr[e] = Aer*Ibr[e-1] - Aei*Ibi[e-1] + bvr[e];
            Ibi[e] = Aer*Ibi[e-1] + Aei*Ibr[e-1] + bvi[e];
        }
    }

    // warp inclusive scan over thread aggregates
    float Ar = IAr[VPT-1], Ai = IAi[VPT-1], br = Ibr[VPT-1], bi = Ibi[VPT-1];
#pragma unroll
    for (int off = 1; off < 32; off <<= 1) {
        float pAr = __shfl_up_sync(0xFFFFFFFFu, Ar, off);
        float pAi = __shfl_up_sync(0xFFFFFFFFu, Ai, off);
        float pbr = __shfl_up_sync(0xFFFFFFFFu, br, off);
        float pbi = __shfl_up_sync(0xFFFFFFFFu, bi, off);
        if (lane >= off) combine_right(Ar, Ai, br, bi, pAr, pAi, pbr, pbi);
    }

    float EwAr = __shfl_up_sync(0xFFFFFFFFu, Ar, 1);
    float EwAi = __shfl_up_sync(0xFFFFFFFFu, Ai, 1);
    float Ewbr = __shfl_up_sync(0xFFFFFFFFu, br, 1);
    float Ewbi = __shfl_up_sync(0xFFFFFFFFu, bi, 1);
    if (lane == 0) { EwAr = 1.0f; EwAi = 0.0f; Ewbr = 0.0f; Ewbi = 0.0f; }

    __shared__ float sW[8][4];
    __shared__ float sPC[2];   // chunk-exclusive prefix b (re, im)
    if (lane == 31) { sW[wid][0] = Ar; sW[wid][1] = Ai; sW[wid][2] = br; sW[wid][3] = bi; }
    __syncthreads();

    // block prefix for this warp
    float PAr = 1.0f, PAi = 0.0f, Pbr = 0.0f, Pbi = 0.0f;
#pragma unroll
    for (int w = 0; w < 7; w++) {
        if (w < wid) {
            float wAr = sW[w][0], wAi = sW[w][1], wbr = sW[w][2], wbi = sW[w][3];
            float nAr = wAr*PAr - wAi*PAi;
            float nAi = wAr*PAi + wAi*PAr;
            float nbr = wAr*Pbr - wAi*Pbi + wbr;
            float nbi = wAr*Pbi + wAi*Pbr + wbi;
            PAr = nAr; PAi = nAi; Pbr = nbr; Pbi = nbi;
        }
    }

    // thread-exclusive within block
    float EAr = EwAr*PAr - EwAi*PAi;
    float EAi = EwAr*PAi + EwAi*PAr;
    float Ebr = EwAr*Pbr - EwAi*Pbi + Ewbr;
    float Ebi = EwAr*Pbi + EwAi*Pbr + Ewbi;

    // ---- decoupled lookback: thread 255 owns publication + lookback ----
    if (tid == SCAN_T - 1) {
        // block aggregate = my inclusive ∘ P
        float gA_r = Ar, gA_i = Ai, gb_r = br, gb_i = bi;
        combine_right(gA_r, gA_i, gb_r, gb_i, PAr, PAi, Pbr, Pbi);

        const int base = (p * NCHUNK + chunk) * 4;
        float exr = 0.0f, exi = 0.0f;   // exclusive prefix b
        if (chunk == 0) {
            volatile float* dp = g_lbP + base;
            dp[0] = gA_r; dp[1] = gA_i; dp[2] = gb_r; dp[3] = gb_i;
            __threadfence();
            *(volatile int*)&g_lbF[p * NCHUNK] = 2;
        } else {
            // publish aggregate first
            volatile float* da = g_lbA + base;
            da[0] = gA_r; da[1] = gA_i; da[2] = gb_r; da[3] = gb_i;
            __threadfence();
            *(volatile int*)&g_lbF[p * NCHUNK + chunk] = 1;

            // lookback
            float RAr = 1.0f, RAi = 0.0f, Rbr = 0.0f, Rbi = 0.0f;  // identity (later side)
            int j = chunk - 1;
            while (true) {
                int f;
                do { f = *(volatile int*)&g_lbF[p * NCHUNK + j]; } while (f == 0);
                if (f == 2) {
                    volatile float* q = g_lbP + (p * NCHUNK + j) * 4;
                    float qa = q[0], qb = q[1], qc = q[2], qd = q[3];
                    combine_right(RAr, RAi, Rbr, Rbi, qa, qb, qc, qd);
                    break;
                } else {
                    volatile float* q = g_lbA + (p * NCHUNK + j) * 4;
                    float qa = q[0], qb = q[1], qc = q[2], qd = q[3];
                    combine_right(RAr, RAi, Rbr, Rbi, qa, qb, qc, qd);
                    j--;
                }
            }
            exr = Rbr; exi = Rbi;
            // publish inclusive prefix: aggregate ∘ R
            combine_right(gA_r, gA_i, gb_r, gb_i, RAr, RAi, Rbr, Rbi);
            volatile float* dp = g_lbP + base;
            dp[0] = gA_r; dp[1] = gA_i; dp[2] = gb_r; dp[3] = gb_i;
            __threadfence();
            *(volatile int*)&g_lbF[p * NCHUNK + chunk] = 2;
        }
        sPC[0] = exr; sPC[1] = exi;
    }
    __syncthreads();

    const float pcr = sPC[0], pci = sPC[1];
    float xpr = EAr*pcr - EAi*pci + Ebr;
    float xpi = EAr*pci + EAi*pcr + Ebi;

    float o_r[VPT], o_i[VPT];
#pragma unroll
    for (int e = 0; e < VPT; e++) {
        o_r[e] = IAr[e]*xpr - IAi[e]*xpi + Ibr[e];
        o_i[e] = IAr[e]*xpi + IAi[e]*xpr + Ibi[e];
    }
    *(uint4*)(g_xrbf + (size_t)p * L_SEQ + l0) =
        make_uint4(packbf(o_r[0], o_r[1]), packbf(o_r[2], o_r[3]),
                   packbf(o_r[4], o_r[5]), packbf(o_r[6], o_r[7]));
    *(uint4*)(g_xibf + (size_t)p * L_SEQ + l0) =
        make_uint4(packbf(o_i[0], o_i[1]), packbf(o_i[2], o_i[3]),
                   packbf(o_i[4], o_i[5]), packbf(o_i[6], o_i[7]));
}

// ======================== pack_x (unchanged) ========================
__global__ __launch_bounds__(256) void pack_x()
{
    int id = blockIdx.x * 256 + threadIdx.x;
    int l4 = id & 8191;
    int kg = (id >> 13) & 15;
    int pl = id >> 17;
    const uint16_t* base = (pl ? g_xibf : g_xrbf) + (size_t)(kg * 16) * L_SEQ + l4 * 4;
    const uint32_t neg = pl ? 0x80008000u : 0u;

    ushort4 fe[8], fo[8];
#pragma unroll
    for (int jp = 0; jp < 8; jp++) {
        fe[jp] = *(const ushort4*)(base + (size_t)(2 * jp) * L_SEQ);
        fo[jp] = *(const ushort4*)(base + (size_t)(2 * jp + 1) * L_SEQ);
    }
    uint32_t* dst = g_xp + ((size_t)(pl * 16 + kg) * L_SEQ + l4 * 4) * 8;
#pragma unroll
    for (int li = 0; li < 4; li++) {
        uint32_t row[8];
#pragma unroll
        for (int jp = 0; jp < 8; jp++) {
            uint16_t e = (li == 0) ? fe[jp].x : (li == 1) ? fe[jp].y : (li == 2) ? fe[jp].z : fe[jp].w;
            uint16_t o = (li == 0) ? fo[jp].x : (li == 1) ? fo[jp].y : (li == 2) ? fo[jp].z : fo[jp].w;
            row[jp] = (((uint32_t)e) | ((uint32_t)o << 16)) ^ neg;
        }
        *(uint4*)(dst + li * 8)     = make_uint4(row[0], row[1], row[2], row[3]);
        *(uint4*)(dst + li * 8 + 4) = make_uint4(row[4], row[5], row[6], row[7]);
    }
}

// ======================== GEMM2 (unchanged from R15) ========================
#define G2_BUFB 24576
#define G2_SMEM_BYTES (3 * G2_BUFB)

__global__ __launch_bounds__(256, 3) void gemm2(
    const float* __restrict__ u, const float* __restrict__ Dg,
    float* __restrict__ out)
{
    extern __shared__ uint32_t sm2[];
    const uint32_t smb = smem_u32(sm2);
    const int tid = threadIdx.x;
    const int wid = tid >> 5, lane = tid & 31;
    const int g = lane >> 2, t = lane & 3;
    const int wm = wid >> 2, wn = wid & 3;
    const int bn = blockIdx.x * 128;
    const int bm = blockIdx.y * 64;

    const int qr = lane & 7, sel = lane >> 3;
    const uint32_t aoff0 = swz(wm * 32 + 0 * 16 + (sel & 1) * 8 + qr, sel >> 1);
    const uint32_t aoff1 = swz(wm * 32 + 1 * 16 + (sel & 1) * 8 + qr, sel >> 1);
    const uint32_t boff0 = swz(wn * 32 + (sel >> 1) * 8 + qr, sel & 1);
    const uint32_t boff1 = swz(wn * 32 + 16 + (sel >> 1) * 8 + qr, sel & 1);

    float acc[2][4][4];
#pragma unroll
    for (int i = 0; i < 2; i++)
#pragma unroll
        for (int j = 0; j < 4; j++)
#pragma unroll
            for (int r = 0; r < 4; r++) acc[i][j][r] = 0.0f;

    auto copy_step = [&](int s, int buf) {
        uint32_t sb = smb + buf * G2_BUFB;
        int kg = 2 * s;
#pragma unroll
        for (int j = 0; j < 2; j++) {
            int c = tid + j * 256;
            int sel2 = c >> 8, cc = c & 255;
            int grp = cc >> 7, off = cc & 127;
            CP_ASYNC16(sb + sel2 * 4096 + grp * 2048 + cswz(off) * 16,
                       (const char*)(g_xp + ((size_t)(sel2 * 16 + kg + grp) * L_SEQ + bm) * 8) + off * 16);
        }
#pragma unroll
        for (int j = 0; j < 4; j++) {
            int c = tid + j * 256;
            int sel2 = c >> 9, cc = c & 511;
            int grp = cc >> 8, off = cc & 255;
            CP_ASYNC16(sb + 8192 + sel2 * 8192 + grp * 4096 + cswz(off) * 16,
                       (const char*)(g_Cp + ((size_t)(sel2 * 16 + kg + grp) * 512 + bn) * 8) + off * 16);
        }
    };

    copy_step(0, 0); CP_COMMIT();
    copy_step(1, 1); CP_COMMIT();

    for (int s = 0; s < 8; s++) {
        if (s < 7) CP_WAIT1(); else CP_WAIT0();
        __syncthreads();
        if (s + 2 < 8) { copy_step(s + 2, (s + 2) % 3); CP_COMMIT(); }

        const uint32_t curb = smb + (s % 3) * G2_BUFB;
#pragma unroll
        for (int k16 = 0; k16 < 2; k16++) {
            uint32_t ar[2][4], ai[2][4];
            LDSM_X4(ar[0][0], ar[0][1], ar[0][2], ar[0][3], curb + k16 * 2048 + aoff0);
            LDSM_X4(ar[1][0], ar[1][1], ar[1][2], ar[1][3], curb + k16 * 2048 + aoff1);
            LDSM_X4(ai[0][0], ai[0][1], ai[0][2], ai[0][3], curb + 4096 + k16 * 2048 + aoff0);
            LDSM_X4(ai[1][0], ai[1][1], ai[1][2], ai[1][3], curb + 4096 + k16 * 2048 + aoff1);
            uint32_t brg[8], big[8];
            uint32_t bb = curb + 8192 + k16 * 4096;
            LDSM_X4(brg[0], brg[1], brg[2], brg[3], bb + boff0);
            LDSM_X4(brg[4], brg[5], brg[6], brg[7], bb + boff1);
            LDSM_X4(big[0], big[1], big[2], big[3], bb + 8192 + boff0);
            LDSM_X4(big[4], big[5], big[6], big[7], bb + 8192 + boff1);
#pragma unroll
            for (int nt = 0; nt < 4; nt++) {
#pragma unroll
                for (int mt = 0; mt < 2; mt++) {
                    mma_bf16(acc[mt][nt], ar[mt], brg[nt * 2], brg[nt * 2 + 1]);
                    mma_bf16(acc[mt][nt], ai[mt], big[nt * 2], big[nt * 2 + 1]);
                }
            }
        }
    }

#pragma unroll
    for (int mt = 0; mt < 2; mt++) {
#pragma unroll
        for (int rh = 0; rh < 2; rh++) {
            int l = bm + wm * 32 + mt * 16 + g + rh * 8;
#pragma unroll
            for (int nt = 0; nt < 4; nt++) {
                int h0 = bn + wn * 32 + nt * 8 + 2 * t;
                float2 uu = *(const float2*)(u + (size_t)l * H_DIM + h0);
                float2 dd = *(const float2*)(Dg + h0);
                float2 o;
                o.x = 2.0f * acc[mt][nt][rh * 2 + 0] + dd.x * uu.x;
                o.y = 2.0f * acc[mt][nt][rh * 2 + 1] + dd.y * uu.y;
                *(float2*)(out + (size_t)l * H_DIM + h0) = o;
            }
        }
    }
}

// ======================== launch ========================
extern "C" void kernel_launch(void* const* d_in, const int* in_sizes, int n_in,
                              void* d_out, int out_size)
{
    const float* u   = (const float*)d_in[0];  // (L, H)
    const float* dtv = (const float*)d_in[1];  // (L,)
    const float* Lre = (const float*)d_in[2];  // (P,)
    const float* Lim = (const float*)d_in[3];  // (P,)
    const float* Bre = (const float*)d_in[4];  // (P, H)
    const float* Bim = (const float*)d_in[5];  // (P, H)
    const float* Cre = (const float*)d_in[6];  // (H, P)
    const float* Cim = (const float*)d_in[7];  // (H, P)
    const float* Dg  = (const float*)d_in[8];  // (H,)
    const float* lst = (const float*)d_in[9];  // (P,)
    float* out = (float*)d_out;                // (L, H)

    static int attr_done = 0;
    if (!attr_done) {
        cudaFuncSetAttribute(gemm1, cudaFuncAttributeMaxDynamicSharedMemorySize, G1_SMEM_BYTES);
        cudaFuncSetAttribute(gemm2, cudaFuncAttributeMaxDynamicSharedMemorySize, G2_SMEM_BYTES);
        attr_done = 1;
    }

    init_flags<<<(P_DIM * NCHUNK) / 256, 256>>>();
    convert_u_p<<<(32 * L_SEQ) / 256, 256>>>(u);
    convert_B_p<<<dim3(32, 2), 256>>>(Bre, Bim);
    convert_C_p<<<dim3(16, 2), 512>>>(Cre, Cim);
    gemm1<<<dim3(P_DIM / 32, L_SEQ / 128), 256, G1_SMEM_BYTES>>>(dtv, Lre, Lim, lst);
    scan_fused<<<dim3(NCHUNK, P_DIM), SCAN_T>>>(dtv, Lre, Lim, lst);
    pack_x<<<(2 * 16 * (L_SEQ / 4)) / 256, 256>>>();
    gemm2<<<dim3(H_DIM / 128, L_SEQ / 64), 256, G2_SMEM_BYTES>>>(u, Dg, out);
}

// round 17
// speedup vs baseline: 1.1222x; 1.1222x over previous
#include <cuda_runtime.h>
#include <math.h>
#include <stdint.h>

#define L_SEQ 32768
#define H_DIM 512
#define P_DIM 256
#define VPT 8
#define SCAN_T 256
#define CHUNK (SCAN_T * VPT)        // 2048
#define NCHUNK (L_SEQ / CHUNK)      // 16

// fp32 scratch planes [P][L]: Bu written by gemm1, read by scan.
__device__ float g_x_re[(size_t)P_DIM * L_SEQ];
__device__ float g_x_im[(size_t)P_DIM * L_SEQ];
__device__ float g_agg[P_DIM * NCHUNK * 4];
__device__ float g_pre[P_DIM * NCHUNK * 2];

// pre-converted bf16 operand images, NATURAL word order: [k16-group][row][8 words]
__device__ uint32_t g_up[(size_t)32 * L_SEQ * 8];        // u:  kg 0..31 (h), row l
__device__ uint32_t g_Bp[2 * 32 * 256 * 8];              // B:  plane, kg (h), row p
__device__ uint32_t g_Cp[2 * 16 * 512 * 8];              // C:  plane, kg (p), row h
// bf16 scanned state planes [P][L] (scan_apply -> pack_x)
__device__ uint16_t g_xrbf[(size_t)P_DIM * L_SEQ];
__device__ uint16_t g_xibf[(size_t)P_DIM * L_SEQ];
// packed gemm2 A image: [plane][kg 0..15][l][8 words], im plane pre-negated
__device__ uint32_t g_xp[(size_t)2 * 16 * L_SEQ * 8];

// ---------------- common helpers ----------------

__device__ __forceinline__ void combine_right(float& Ar, float& Ai, float& br, float& bi,
                                              float pAr, float pAi, float pbr, float pbi)
{
    float nAr = Ar*pAr - Ai*pAi;
    float nAi = Ar*pAi + Ai*pAr;
    float nbr = Ar*pbr - Ai*pbi + br;
    float nbi = Ar*pbi + Ai*pbr + bi;
    Ar = nAr; Ai = nAi; br = nbr; bi = nbi;
}

__device__ __forceinline__ void combine_left(float& Ar, float& Ai, float& br, float& bi,
                                             float rAr, float rAi, float rbr, float rbi)
{
    float nAr = rAr*Ar - rAi*Ai;
    float nAi = rAr*Ai + rAi*Ar;
    float nbr = rAr*br - rAi*bi + rbr;
    float nbi = rAr*bi + rAi*br + rbi;
    Ar = nAr; Ai = nAi; br = nbr; bi = nbi;
}

__device__ __forceinline__ void lambda_bar(float lre, float lim, float Dl, float& Ar, float& Ai)
{
    float e = expf(lre * Dl);
    float s, c;
    sincosf(lim * Dl, &s, &c);
    Ar = e * c;
    Ai = e * s;
}

__device__ __forceinline__ uint32_t packbf(float lo, float hi)
{
    uint32_t r;
    asm("cvt.rn.bf16x2.f32 %0, %1, %2;" : "=r"(r) : "f"(hi), "f"(lo));
    return r;
}

__device__ __forceinline__ void mma_bf16(float* d, const uint32_t* a, uint32_t b0, uint32_t b1)
{
    asm volatile(
        "mma.sync.aligned.m16n8k16.row.col.f32.bf16.bf16.f32 "
        "{%0,%1,%2,%3}, {%4,%5,%6,%7}, {%8,%9}, {%0,%1,%2,%3};"
        : "+f"(d[0]), "+f"(d[1]), "+f"(d[2]), "+f"(d[3])
        : "r"(a[0]), "r"(a[1]), "r"(a[2]), "r"(a[3]), "r"(b0), "r"(b1));
}

#define LDSM_X4(r0, r1, r2, r3, addr) \
    asm volatile("ldmatrix.sync.aligned.m8n8.x4.shared.b16 {%0,%1,%2,%3}, [%4];" \
                 : "=r"(r0), "=r"(r1), "=r"(r2), "=r"(r3) : "r"(addr))

__device__ __forceinline__ uint32_t smem_u32(const void* p) {
    uint32_t a;
    asm("{ .reg .u64 t; cvta.to.shared.u64 t, %1; cvt.u32.u64 %0, t; }" : "=r"(a) : "l"(p));
    return a;
}

// byte offset of (row, k-half) within a kg region; 16B-granule XOR swizzle
__device__ __forceinline__ uint32_t swz(int row, int half)
{
    return (uint32_t)(row * 32 + ((half ^ ((row >> 2) & 1)) << 4));
}

#define CP_ASYNC16(dst, src) \
    asm volatile("cp.async.cg.shared.global [%0], [%1], 16;" :: "r"(dst), "l"(src) : "memory")
#define CP_COMMIT() asm volatile("cp.async.commit_group;" ::: "memory")
#define CP_WAIT1()  asm volatile("cp.async.wait_group 1;" ::: "memory")
#define CP_WAIT0()  asm volatile("cp.async.wait_group 0;" ::: "memory")

// chunk-index swizzle (chunk = row*2 + half)
__device__ __forceinline__ int cswz(int c) { return c ^ ((c >> 3) & 1); }

// ======================== converters (natural word order) ========================
__global__ __launch_bounds__(256) void convert_u_p(const float* __restrict__ u)
{
    int id = blockIdx.x * 256 + threadIdx.x;   // 32 kg x 32768 l
    int kg = id >> 15;
    int l  = id & 32767;
    const float* src = u + (size_t)l * H_DIM + kg * 16;
    float4 v0 = *(const float4*)(src + 0);
    float4 v1 = *(const float4*)(src + 4);
    float4 v2 = *(const float4*)(src + 8);
    float4 v3 = *(const float4*)(src + 12);
    uint32_t* dst = g_up + ((size_t)kg * L_SEQ + l) * 8;
    *(uint4*)(dst)     = make_uint4(packbf(v0.x, v0.y), packbf(v0.z, v0.w),
                                    packbf(v1.x, v1.y), packbf(v1.z, v1.w));
    *(uint4*)(dst + 4) = make_uint4(packbf(v2.x, v2.y), packbf(v2.z, v2.w),
                                    packbf(v3.x, v3.y), packbf(v3.z, v3.w));
}

__global__ __launch_bounds__(256) void convert_B_p(
    const float* __restrict__ Bre, const float* __restrict__ Bim)
{
    int kg = blockIdx.x;
    int pl = blockIdx.y;
    int p  = threadIdx.x;
    const float* src = (pl ? Bim : Bre) + (size_t)p * H_DIM + kg * 16;
    float4 v0 = *(const float4*)(src + 0);
    float4 v1 = *(const float4*)(src + 4);
    float4 v2 = *(const float4*)(src + 8);
    float4 v3 = *(const float4*)(src + 12);
    uint32_t* dst = g_Bp + ((size_t)(pl * 32 + kg) * 256 + p) * 8;
    *(uint4*)(dst)     = make_uint4(packbf(v0.x, v0.y), packbf(v0.z, v0.w),
                                    packbf(v1.x, v1.y), packbf(v1.z, v1.w));
    *(uint4*)(dst + 4) = make_uint4(packbf(v2.x, v2.y), packbf(v2.z, v2.w),
                                    packbf(v3.x, v3.y), packbf(v3.z, v3.w));
}

__global__ __launch_bounds__(512) void convert_C_p(
    const float* __restrict__ Cre, const float* __restrict__ Cim)
{
    int kg = blockIdx.x;
    int pl = blockIdx.y;
    int h  = threadIdx.x;
    const float* src = (pl ? Cim : Cre) + (size_t)h * P_DIM + kg * 16;
    float4 v0 = *(const float4*)(src + 0);
    float4 v1 = *(const float4*)(src + 4);
    float4 v2 = *(const float4*)(src + 8);
    float4 v3 = *(const float4*)(src + 12);
    uint32_t* dst = g_Cp + ((size_t)(pl * 16 + kg) * 512 + h) * 8;
    *(uint4*)(dst)     = make_uint4(packbf(v0.x, v0.y), packbf(v0.z, v0.w),
                                    packbf(v1.x, v1.y), packbf(v1.z, v1.w));
    *(uint4*)(dst + 4) = make_uint4(packbf(v2.x, v2.y), packbf(v2.z, v2.w),
                                    packbf(v3.x, v3.y), packbf(v3.z, v3.w));
}

// ======================== GEMM1: BM=64, BN=64, 3 CTA/SM, 3-stage cp.async + ldmatrix ==========
// Bu = gamma_bar * (u @ B^T). Warp grid 2m x 4n, warp tile 32l x 16p. 16 steps.
// Buffer bytes: A[0..4095] (2kg x 64row x 32B), Br[4096..8191], Bi[8192..12287]
#define G1_BUFB 12288
#define G1_SMEM_BYTES (3 * G1_BUFB)   // 36864

__global__ __launch_bounds__(256, 3) void gemm1(
    const float* __restrict__ dtv, const float* __restrict__ Lre_g, const float* __restrict__ Lim_g,
    const float* __restrict__ logstep)
{
    extern __shared__ uint32_t sm1[];
    const uint32_t smb = smem_u32(sm1);
    const int tid = threadIdx.x;
    const int wid = tid >> 5, lane = tid & 31;
    const int g = lane >> 2, t = lane & 3;
    const int wm = wid >> 2, wn = wid & 3;     // 2m x 4n, warp tile 32l x 16p
    const int bm = blockIdx.y * 64;
    const int bn = blockIdx.x * 64;

    const int qr = lane & 7, sel = lane >> 3;
    const uint32_t aoff0 = swz(wm * 32 + 0 * 16 + (sel & 1) * 8 + qr, sel >> 1);
    const uint32_t aoff1 = swz(wm * 32 + 1 * 16 + (sel & 1) * 8 + qr, sel >> 1);
    const uint32_t boff  = swz(wn * 16 + (sel >> 1) * 8 + qr, sel & 1);

    float accr[2][2][4];
    float acci[2][2][4];
#pragma unroll
    for (int i = 0; i < 2; i++)
#pragma unroll
        for (int j = 0; j < 2; j++)
#pragma unroll
            for (int r = 0; r < 4; r++) { accr[i][j][r] = 0.0f; acci[i][j][r] = 0.0f; }

    auto copy_step = [&](int s, int buf) {
        uint32_t sb = smb + buf * G1_BUFB;
        int kg = 2 * s;
        // A: 256 chunks (2kg x 64row x 2half)
        {
            int grp = tid >> 7, off = tid & 127;
            CP_ASYNC16(sb + grp * 2048 + cswz(off) * 16,
                       (const char*)(g_up + ((size_t)(kg + grp) * L_SEQ + bm) * 8) + off * 16);
        }
        // Br/Bi: 512 chunks (2pl x 2kg x 64row x 2half)
#pragma unroll
        for (int j = 0; j < 2; j++) {
            int c = tid + j * 256;
            int pl = c >> 8, rem = c & 255;
            int grp = rem >> 7, off = rem & 127;
            CP_ASYNC16(sb + 4096 + pl * 4096 + grp * 2048 + cswz(off) * 16,
                       (const char*)(g_Bp + ((size_t)(pl * 32 + kg + grp) * 256 + bn) * 8) + off * 16);
        }
    };

    copy_step(0, 0); CP_COMMIT();
    copy_step(1, 1); CP_COMMIT();

    for (int s = 0; s < 16; s++) {
        if (s < 15) CP_WAIT1(); else CP_WAIT0();
        __syncthreads();
        if (s + 2 < 16) { copy_step(s + 2, (s + 2) % 3); CP_COMMIT(); }

        const uint32_t curb = smb + (s % 3) * G1_BUFB;
#pragma unroll
        for (int k16 = 0; k16 < 2; k16++) {
            uint32_t a[2][4];
            LDSM_X4(a[0][0], a[0][1], a[0][2], a[0][3], curb + k16 * 2048 + aoff0);
            LDSM_X4(a[1][0], a[1][1], a[1][2], a[1][3], curb + k16 * 2048 + aoff1);
            uint32_t brg[4], big[4];
            uint32_t bb = curb + 4096 + k16 * 2048 + boff;
            LDSM_X4(brg[0], brg[1], brg[2], brg[3], bb);
            LDSM_X4(big[0], big[1], big[2], big[3], bb + 4096);
#pragma unroll
            for (int nt = 0; nt < 2; nt++) {
#pragma unroll
                for (int mt = 0; mt < 2; mt++) {
                    mma_bf16(accr[mt][nt], a[mt], brg[nt * 2], brg[nt * 2 + 1]);
                    mma_bf16(acci[mt][nt], a[mt], big[nt * 2], big[nt * 2 + 1]);
                }
            }
        }
    }

    // epilogue: gamma_bar multiply, store fp32 Bu to [P][L] planes
    float dts[2][2];
#pragma unroll
    for (int mt = 0; mt < 2; mt++)
#pragma unroll
        for (int rh = 0; rh < 2; rh++)
            dts[mt][rh] = dtv[bm + wm * 32 + mt * 16 + g + rh * 8];

#pragma unroll
    for (int nt = 0; nt < 2; nt++) {
#pragma unroll
        for (int c = 0; c < 2; c++) {
            int p = bn + wn * 16 + nt * 8 + 2 * t + c;
            float lre = Lre_g[p], lim = Lim_g[p];
            float stp = expf(logstep[p]);
            float inv = 1.0f / (lre * lre + lim * lim);
#pragma unroll
            for (int mt = 0; mt < 2; mt++) {
#pragma unroll
                for (int rh = 0; rh < 2; rh++) {
                    int l = bm + wm * 32 + mt * 16 + g + rh * 8;
                    float Dl = dts[mt][rh] * stp;
                    float Ar, Ai;
                    lambda_bar(lre, lim, Dl, Ar, Ai);
                    float gr = ((Ar - 1.0f) * lre + Ai * lim) * inv;
                    float gi = (Ai * lre - (Ar - 1.0f) * lim) * inv;
                    int reg = rh * 2 + c;
                    float ar = accr[mt][nt][reg], ai = acci[mt][nt][reg];
                    size_t o = (size_t)p * L_SEQ + l;
                    g_x_re[o] = gr * ar - gi * ai;
                    g_x_im[o] = gr * ai + gi * ar;
                }
            }
        }
    }
}

// ======================== Scan phase A (R15-proven) ========================
__global__ __launch_bounds__(SCAN_T) void scan_agg(
    const float* __restrict__ dtv, const float* __restrict__ Lre_g,
    const float* __restrict__ Lim_g, const float* __restrict__ logstep)
{
    const int p = blockIdx.y;
    const int chunk = blockIdx.x;
    const int tid = threadIdx.x;
    const int l0 = chunk * CHUNK + tid * VPT;

    const float lre = Lre_g[p], lim = Lim_g[p];
    const float stp = expf(logstep[p]);
    const float* xr = g_x_re + (size_t)p * L_SEQ + l0;
    const float* xi = g_x_im + (size_t)p * L_SEQ + l0;

    float dt[VPT], bvr[VPT], bvi[VPT];
    {
        float4 d0 = *(const float4*)(dtv + l0);
        float4 d1 = *(const float4*)(dtv + l0 + 4);
        dt[0]=d0.x; dt[1]=d0.y; dt[2]=d0.z; dt[3]=d0.w;
        dt[4]=d1.x; dt[5]=d1.y; dt[6]=d1.z; dt[7]=d1.w;
        float4 r0 = *(const float4*)(xr), r1 = *(const float4*)(xr + 4);
        bvr[0]=r0.x; bvr[1]=r0.y; bvr[2]=r0.z; bvr[3]=r0.w;
        bvr[4]=r1.x; bvr[5]=r1.y; bvr[6]=r1.z; bvr[7]=r1.w;
        float4 i0 = *(const float4*)(xi), i1 = *(const float4*)(xi + 4);
        bvi[0]=i0.x; bvi[1]=i0.y; bvi[2]=i0.z; bvi[3]=i0.w;
        bvi[4]=i1.x; bvi[5]=i1.y; bvi[6]=i1.z; bvi[7]=i1.w;
    }

    float Ar, Ai, br, bi;
    lambda_bar(lre, lim, dt[0] * stp, Ar, Ai);
    br = bvr[0]; bi = bvi[0];
#pragma unroll
    for (int e = 1; e < VPT; e++) {
        float Aer, Aei;
        lambda_bar(lre, lim, dt[e] * stp, Aer, Aei);
        float nAr = Aer*Ar - Aei*Ai;
        float nAi = Aer*Ai + Aei*Ar;
        float nbr = Aer*br - Aei*bi + bvr[e];
        float nbi = Aer*bi + Aei*br + bvi[e];
        Ar = nAr; Ai = nAi; br = nbr; bi = nbi;
    }

#pragma unroll
    for (int off = 1; off < 32; off <<= 1) {
        float rAr = __shfl_down_sync(0xFFFFFFFFu, Ar, off);
        float rAi = __shfl_down_sync(0xFFFFFFFFu, Ai, off);
        float rbr = __shfl_down_sync(0xFFFFFFFFu, br, off);
        float rbi = __shfl_down_sync(0xFFFFFFFFu, bi, off);
        combine_left(Ar, Ai, br, bi, rAr, rAi, rbr, rbi);
    }

    __shared__ float sA_r[8], sA_i[8], sb_r[8], sb_i[8];
    int lane = tid & 31, wid = tid >> 5;
    if (lane == 0) { sA_r[wid] = Ar; sA_i[wid] = Ai; sb_r[wid] = br; sb_i[wid] = bi; }
    __syncthreads();

    if (wid == 0) {
        float aAr = (lane < 8) ? sA_r[lane] : 1.0f;
        float aAi = (lane < 8) ? sA_i[lane] : 0.0f;
        float abr = (lane < 8) ? sb_r[lane] : 0.0f;
        float abi = (lane < 8) ? sb_i[lane] : 0.0f;
#pragma unroll
        for (int off = 1; off < 8; off <<= 1) {
            float rAr = __shfl_down_sync(0xFFFFFFFFu, aAr, off);
            float rAi = __shfl_down_sync(0xFFFFFFFFu, aAi, off);
            float rbr = __shfl_down_sync(0xFFFFFFFFu, abr, off);
            float rbi = __shfl_down_sync(0xFFFFFFFFu, abi, off);
            combine_left(aAr, aAi, abr, abi, rAr, rAi, rbr, rbi);
        }
        if (lane == 0) {
            size_t o = ((size_t)p * NCHUNK + chunk) * 4;
            g_agg[o + 0] = aAr; g_agg[o + 1] = aAi;
            g_agg[o + 2] = abr; g_agg[o + 3] = abi;
        }
    }
}

// ======================== Scan phase B ========================
__global__ __launch_bounds__(32) void chunk_prefix()
{
    const int p = blockIdx.x;
    const int lane = threadIdx.x;

    float Ar = 1.0f, Ai = 0.0f, br = 0.0f, bi = 0.0f;
    if (lane < NCHUNK) {
        size_t o = ((size_t)p * NCHUNK + lane) * 4;
        Ar = g_agg[o + 0]; Ai = g_agg[o + 1];
        br = g_agg[o + 2]; bi = g_agg[o + 3];
    }

#pragma unroll
    for (int off = 1; off < NCHUNK; off <<= 1) {
        float pAr = __shfl_up_sync(0xFFFFFFFFu, Ar, off);
        float pAi = __shfl_up_sync(0xFFFFFFFFu, Ai, off);
        float pbr = __shfl_up_sync(0xFFFFFFFFu, br, off);
        float pbi = __shfl_up_sync(0xFFFFFFFFu, bi, off);
        if (lane >= off) combine_right(Ar, Ai, br, bi, pAr, pAi, pbr, pbi);
    }

    float er = __shfl_up_sync(0xFFFFFFFFu, br, 1);
    float ei = __shfl_up_sync(0xFFFFFFFFu, bi, 1);
    if (lane == 0) { er = 0.0f; ei = 0.0f; }
    if (lane < NCHUNK) {
        size_t q = ((size_t)p * NCHUNK + lane) * 2;
        g_pre[q] = er; g_pre[q + 1] = ei;
    }
}

// ======================== Scan phase C (R15-proven) ========================
__global__ __launch_bounds__(SCAN_T) void scan_apply(
    const float* __restrict__ dtv, const float* __restrict__ Lre_g,
    const float* __restrict__ Lim_g, const float* __restrict__ logstep)
{
    const int p = blockIdx.y;
    const int chunk = blockIdx.x;
    const int tid = threadIdx.x;
    const int l0 = chunk * CHUNK + tid * VPT;
    const int lane = tid & 31, wid = tid >> 5;

    const float lre = Lre_g[p], lim = Lim_g[p];
    const float stp = expf(logstep[p]);
    const float* xr = g_x_re + (size_t)p * L_SEQ + l0;
    const float* xi = g_x_im + (size_t)p * L_SEQ + l0;

    float dt[VPT], bvr[VPT], bvi[VPT];
    {
        float4 d0 = *(const float4*)(dtv + l0);
        float4 d1 = *(const float4*)(dtv + l0 + 4);
        dt[0]=d0.x; dt[1]=d0.y; dt[2]=d0.z; dt[3]=d0.w;
        dt[4]=d1.x; dt[5]=d1.y; dt[6]=d1.z; dt[7]=d1.w;
        float4 r0 = *(const float4*)(xr), r1 = *(const float4*)(xr + 4);
        bvr[0]=r0.x; bvr[1]=r0.y; bvr[2]=r0.z; bvr[3]=r0.w;
        bvr[4]=r1.x; bvr[5]=r1.y; bvr[6]=r1.z; bvr[7]=r1.w;
        float4 i0 = *(const float4*)(xi), i1 = *(const float4*)(xi + 4);
        bvi[0]=i0.x; bvi[1]=i0.y; bvi[2]=i0.z; bvi[3]=i0.w;
        bvi[4]=i1.x; bvi[5]=i1.y; bvi[6]=i1.z; bvi[7]=i1.w;
    }

    float IAr[VPT], IAi[VPT], Ibr[VPT], Ibi[VPT];
    {
        float Aer, Aei;
        lambda_bar(lre, lim, dt[0] * stp, Aer, Aei);
        IAr[0] = Aer; IAi[0] = Aei; Ibr[0] = bvr[0]; Ibi[0] = bvi[0];
#pragma unroll
        for (int e = 1; e < VPT; e++) {
            lambda_bar(lre, lim, dt[e] * stp, Aer, Aei);
            IAr[e] = Aer*IAr[e-1] - Aei*IAi[e-1];
            IAi[e] = Aer*IAi[e-1] + Aei*IAr[e-1];
            Ibr[e] = Aer*Ibr[e-1] - Aei*Ibi[e-1] + bvr[e];
            Ibi[e] = Aer*Ibi[e-1] + Aei*Ibr[e-1] + bvi[e];
        }
    }

    float Ar = IAr[VPT-1], Ai = IAi[VPT-1], br = Ibr[VPT-1], bi = Ibi[VPT-1];
#pragma unroll
    for (int off = 1; off < 32; off <<= 1) {
        float pAr = __shfl_up_sync(0xFFFFFFFFu, Ar, off);
        float pAi = __shfl_up_sync(0xFFFFFFFFu, Ai, off);
        float pbr = __shfl_up_sync(0xFFFFFFFFu, br, off);
        float pbi = __shfl_up_sync(0xFFFFFFFFu, bi, off);
        if (lane >= off) combine_right(Ar, Ai, br, bi, pAr, pAi, pbr, pbi);
    }

    float EwAr = __shfl_up_sync(0xFFFFFFFFu, Ar, 1);
    float EwAi = __shfl_up_sync(0xFFFFFFFFu, Ai, 1);
    float Ewbr = __shfl_up_sync(0xFFFFFFFFu, br, 1);
    float Ewbi = __shfl_up_sync(0xFFFFFFFFu, bi, 1);
    if (lane == 0) { EwAr = 1.0f; EwAi = 0.0f; Ewbr = 0.0f; Ewbi = 0.0f; }

    __shared__ float sW[8][4];
    if (lane == 31) { sW[wid][0] = Ar; sW[wid][1] = Ai; sW[wid][2] = br; sW[wid][3] = bi; }
    __syncthreads();

    float PAr = 1.0f, PAi = 0.0f, Pbr = 0.0f, Pbi = 0.0f;
#pragma unroll
    for (int w = 0; w < 7; w++) {
        if (w < wid) {
            float wAr = sW[w][0], wAi = sW[w][1], wbr = sW[w][2], wbi = sW[w][3];
            float nAr = wAr*PAr - wAi*PAi;
            float nAi = wAr*PAi + wAi*PAr;
            float nbr = wAr*Pbr - wAi*Pbi + wbr;
            float nbi = wAr*Pbi + wAi*Pbr + wbi;
            PAr = nAr; PAi = nAi; Pbr = nbr; Pbi = nbi;
        }
    }

    float EAr = EwAr*PAr - EwAi*PAi;
    float EAi = EwAr*PAi + EwAi*PAr;
    float Ebr = EwAr*Pbr - EwAi*Pbi + Ewbr;
    float Ebi = EwAr*Pbi + EwAi*Pbr + Ewbi;

    size_t q = ((size_t)p * NCHUNK + chunk) * 2;
    float pcr = g_pre[q], pci = g_pre[q + 1];
    float xpr = EAr*pcr - EAi*pci + Ebr;
    float xpi = EAr*pci + EAi*pcr + Ebi;

    float o_r[VPT], o_i[VPT];
#pragma unroll
    for (int e = 0; e < VPT; e++) {
        o_r[e] = IAr[e]*xpr - IAi[e]*xpi + Ibr[e];
        o_i[e] = IAr[e]*xpi + IAi[e]*xpr + Ibi[e];
    }
    *(uint4*)(g_xrbf + (size_t)p * L_SEQ + l0) =
        make_uint4(packbf(o_r[0], o_r[1]), packbf(o_r[2], o_r[3]),
                   packbf(o_r[4], o_r[5]), packbf(o_r[6], o_r[7]));
    *(uint4*)(g_xibf + (size_t)p * L_SEQ + l0) =
        make_uint4(packbf(o_i[0], o_i[1]), packbf(o_i[2], o_i[3]),
                   packbf(o_i[4], o_i[5]), packbf(o_i[6], o_i[7]));
}

// ======================== pack_x (unchanged) ========================
__global__ __launch_bounds__(256) void pack_x()
{
    int id = blockIdx.x * 256 + threadIdx.x;
    int l4 = id & 8191;
    int kg = (id >> 13) & 15;
    int pl = id >> 17;
    const uint16_t* base = (pl ? g_xibf : g_xrbf) + (size_t)(kg * 16) * L_SEQ + l4 * 4;
    const uint32_t neg = pl ? 0x80008000u : 0u;

    ushort4 fe[8], fo[8];
#pragma unroll
    for (int jp = 0; jp < 8; jp++) {
        fe[jp] = *(const ushort4*)(base + (size_t)(2 * jp) * L_SEQ);
        fo[jp] = *(const ushort4*)(base + (size_t)(2 * jp + 1) * L_SEQ);
    }
    uint32_t* dst = g_xp + ((size_t)(pl * 16 + kg) * L_SEQ + l4 * 4) * 8;
#pragma unroll
    for (int li = 0; li < 4; li++) {
        uint32_t row[8];
#pragma unroll
        for (int jp = 0; jp < 8; jp++) {
            uint16_t e = (li == 0) ? fe[jp].x : (li == 1) ? fe[jp].y : (li == 2) ? fe[jp].z : fe[jp].w;
            uint16_t o = (li == 0) ? fo[jp].x : (li == 1) ? fo[jp].y : (li == 2) ? fo[jp].z : fo[jp].w;
            row[jp] = (((uint32_t)e) | ((uint32_t)o << 16)) ^ neg;
        }
        *(uint4*)(dst + li * 8)     = make_uint4(row[0], row[1], row[2], row[3]);
        *(uint4*)(dst + li * 8 + 4) = make_uint4(row[4], row[5], row[6], row[7]);
    }
}

// ======================== GEMM2 (R15-proven) ========================
#define G2_BUFB 24576
#define G2_SMEM_BYTES (3 * G2_BUFB)

__global__ __launch_bounds__(256, 3) void gemm2(
    const float* __restrict__ u, const float* __restrict__ Dg,
    float* __restrict__ out)
{
    extern __shared__ uint32_t sm2[];
    const uint32_t smb = smem_u32(sm2);
    const int tid = threadIdx.x;
    const int wid = tid >> 5, lane = tid & 31;
    const int g = lane >> 2, t = lane & 3;
    const int wm = wid >> 2, wn = wid & 3;
    const int bn = blockIdx.x * 128;
    const int bm = blockIdx.y * 64;

    const int qr = lane & 7, sel = lane >> 3;
    const uint32_t aoff0 = swz(wm * 32 + 0 * 16 + (sel & 1) * 8 + qr, sel >> 1);
    const uint32_t aoff1 = swz(wm * 32 + 1 * 16 + (sel & 1) * 8 + qr, sel >> 1);
    const uint32_t boff0 = swz(wn * 32 + (sel >> 1) * 8 + qr, sel & 1);
    const uint32_t boff1 = swz(wn * 32 + 16 + (sel >> 1) * 8 + qr, sel & 1);

    float acc[2][4][4];
#pragma unroll
    for (int i = 0; i < 2; i++)
#pragma unroll
        for (int j = 0; j < 4; j++)
#pragma unroll
            for (int r = 0; r < 4; r++) acc[i][j][r] = 0.0f;

    auto copy_step = [&](int s, int buf) {
        uint32_t sb = smb + buf * G2_BUFB;
        int kg = 2 * s;
#pragma unroll
        for (int j = 0; j < 2; j++) {
            int c = tid + j * 256;
            int sel2 = c >> 8, cc = c & 255;
            int grp = cc >> 7, off = cc & 127;
            CP_ASYNC16(sb + sel2 * 4096 + grp * 2048 + cswz(off) * 16,
                       (const char*)(g_xp + ((size_t)(sel2 * 16 + kg + grp) * L_SEQ + bm) * 8) + off * 16);
        }
#pragma unroll
        for (int j = 0; j < 4; j++) {
            int c = tid + j * 256;
            int sel2 = c >> 9, cc = c & 511;
            int grp = cc >> 8, off = cc & 255;
            CP_ASYNC16(sb + 8192 + sel2 * 8192 + grp * 4096 + cswz(off) * 16,
                       (const char*)(g_Cp + ((size_t)(sel2 * 16 + kg + grp) * 512 + bn) * 8) + off * 16);
        }
    };

    copy_step(0, 0); CP_COMMIT();
    copy_step(1, 1); CP_COMMIT();

    for (int s = 0; s < 8; s++) {
        if (s < 7) CP_WAIT1(); else CP_WAIT0();
        __syncthreads();
        if (s + 2 < 8) { copy_step(s + 2, (s + 2) % 3); CP_COMMIT(); }

        const uint32_t curb = smb + (s % 3) * G2_BUFB;
#pragma unroll
        for (int k16 = 0; k16 < 2; k16++) {
            uint32_t ar[2][4], ai[2][4];
            LDSM_X4(ar[0][0], ar[0][1], ar[0][2], ar[0][3], curb + k16 * 2048 + aoff0);
            LDSM_X4(ar[1][0], ar[1][1], ar[1][2], ar[1][3], curb + k16 * 2048 + aoff1);
            LDSM_X4(ai[0][0], ai[0][1], ai[0][2], ai[0][3], curb + 4096 + k16 * 2048 + aoff0);
            LDSM_X4(ai[1][0], ai[1][1], ai[1][2], ai[1][3], curb + 4096 + k16 * 2048 + aoff1);
            uint32_t brg[8], big[8];
            uint32_t bb = curb + 8192 + k16 * 4096;
            LDSM_X4(brg[0], brg[1], brg[2], brg[3], bb + boff0);
            LDSM_X4(brg[4], brg[5], brg[6], brg[7], bb + boff1);
            LDSM_X4(big[0], big[1], big[2], big[3], bb + 8192 + boff0);
            LDSM_X4(big[4], big[5], big[6], big[7], bb + 8192 + boff1);
#pragma unroll
            for (int nt = 0; nt < 4; nt++) {
#pragma unroll
                for (int mt = 0; mt < 2; mt++) {
                    mma_bf16(acc[mt][nt], ar[mt], brg[nt * 2], brg[nt * 2 + 1]);
                    mma_bf16(acc[mt][nt], ai[mt], big[nt * 2], big[nt * 2 + 1]);
                }
            }
        }
    }

#pragma unroll
    for (int mt = 0; mt < 2; mt++) {
#pragma unroll
        for (int rh = 0; rh < 2; rh++) {
            int l = bm + wm * 32 + mt * 16 + g + rh * 8;
#pragma unroll
            for (int nt = 0; nt < 4; nt++) {
                int h0 = bn + wn * 32 + nt * 8 + 2 * t;
                float2 uu = *(const float2*)(u + (size_t)l * H_DIM + h0);
                float2 dd = *(const float2*)(Dg + h0);
                float2 o;
                o.x = 2.0f * acc[mt][nt][rh * 2 + 0] + dd.x * uu.x;
                o.y = 2.0f * acc[mt][nt][rh * 2 + 1] + dd.y * uu.y;
                *(float2*)(out + (size_t)l * H_DIM + h0) = o;
            }
        }
    }
}

// ======================== launch ========================
extern "C" void kernel_launch(void* const* d_in, const int* in_sizes, int n_in,
                              void* d_out, int out_size)
{
    const float* u   = (const float*)d_in[0];  // (L, H)
    const float* dtv = (const float*)d_in[1];  // (L,)
    const float* Lre = (const float*)d_in[2];  // (P,)
    const float* Lim = (const float*)d_in[3];  // (P,)
    const float* Bre = (const float*)d_in[4];  // (P, H)
    const float* Bim = (const float*)d_in[5];  // (P, H)
    const float* Cre = (const float*)d_in[6];  // (H, P)
    const float* Cim = (const float*)d_in[7];  // (H, P)
    const float* Dg  = (const float*)d_in[8];  // (H,)
    const float* lst = (const float*)d_in[9];  // (P,)
    float* out = (float*)d_out;                // (L, H)

    static int attr_done = 0;
    if (!attr_done) {
        cudaFuncSetAttribute(gemm1, cudaFuncAttributeMaxDynamicSharedMemorySize, G1_SMEM_BYTES);
        cudaFuncSetAttribute(gemm2, cudaFuncAttributeMaxDynamicSharedMemorySize, G2_SMEM_BYTES);
        attr_done = 1;
    }

    convert_u_p<<<(32 * L_SEQ) / 256, 256>>>(u);
    convert_B_p<<<dim3(32, 2), 256>>>(Bre, Bim);
    convert_C_p<<<dim3(16, 2), 512>>>(Cre, Cim);
    gemm1<<<dim3(P_DIM / 64, L_SEQ / 64), 256, G1_SMEM_BYTES>>>(dtv, Lre, Lim, lst);
    scan_agg<<<dim3(NCHUNK, P_DIM), SCAN_T>>>(dtv, Lre, Lim, lst);
    chunk_prefix<<<P_DIM, 32>>>();
    scan_apply<<<dim3(NCHUNK, P_DIM), SCAN_T>>>(dtv, Lre, Lim, lst);
    pack_x<<<(2 * 16 * (L_SEQ / 4)) / 256, 256>>>();
    gemm2<<<dim3(H_DIM / 128, L_SEQ / 64), 256, G2_SMEM_BYTES>>>(u, Dg, out);
}